// round 8
// baseline (speedup 1.0000x reference)
#include <cuda_runtime.h>
#include <cuda_fp16.h>

#define BB 4
#define SS 512
#define HH 256
#define H4 (HH / 4)        // 64 groups of 4 h-elements
#define NTILE 4            // tp tiles (128 tp each)
#define TPT 128            // tp per tile
#define RG 16              // t-rows per score block

// Scratch (allocation-free rule -> __device__ globals)
__device__ __half g_ht_h[BB * SS * HH];        // [bt][h]  ht + b_h, half
__device__ uint2  g_htpT[BB * H4 * SS];        // [b][h4][tp] packed halves of htp
__device__ float  g_p[BB * SS * SS];           // unnormalized exp(sigmoid(score))
__device__ float  g_opart[NTILE][BB * SS * HH];// per-tile partial out GEMM
__device__ float  g_rsump[NTILE][BB * SS];     // per-tile partial row sums

__device__ __forceinline__ float tanh_fast(float x) {
    float y; asm("tanh.approx.f32 %0, %1;" : "=f"(y) : "f"(x)); return y;
}
__device__ __forceinline__ unsigned tanh2u(unsigned x) {
    unsigned y; asm("tanh.approx.f16x2 %0, %1;" : "=r"(y) : "r"(x)); return y;
}
__device__ __forceinline__ __half2 u2h(unsigned x) { return *reinterpret_cast<__half2*>(&x); }
__device__ __forceinline__ unsigned h2u(__half2 x) { return *reinterpret_cast<unsigned*>(&x); }

__device__ __forceinline__ void cp_async16(void* smem_dst, const void* gmem_src) {
    unsigned saddr = (unsigned)__cvta_generic_to_shared(smem_dst);
    asm volatile("cp.async.cg.shared.global [%0], [%1], 16;" :: "r"(saddr), "l"(gmem_src));
}
__device__ __forceinline__ void cp_commit() { asm volatile("cp.async.commit_group;"); }
template <int N>
__device__ __forceinline__ void cp_wait() { asm volatile("cp.async.wait_group %0;" :: "n"(N)); }

// ---------------------------------------------------------------------------
// Stage 1: projections (unchanged from R7: cp.async double-buffered W).
// ---------------------------------------------------------------------------
__global__ void __launch_bounds__(512)
proj_kernel(const float* __restrict__ h,
            const float* __restrict__ Wt,
            const float* __restrict__ Wtp,
            const float* __restrict__ bh)
{
    constexpr int ROWS = 8;
    constexpr int THH  = 8;
    constexpr int NT   = HH / THH;
    __shared__ float sh[ROWS][HH];
    __shared__ float sW[2][2][THH][HH];

    const int row0 = blockIdx.x * ROWS;
    const int tid  = threadIdx.x;
    const int half = tid >> 8;
    const int k    = tid & 255;

    for (int i = tid; i < ROWS * HH; i += 512)
        sh[i >> 8][i & 255] = h[row0 * HH + i];

    const float* __restrict__ Wsrc[2] = { Wt, Wtp };
    {
#pragma unroll
        for (int pass = 0; pass < 2; ++pass) {
            const int f  = tid + pass * 512;
            const int hf = f >> 9;
            const int hhq= (f >> 6) & 7;
            const int k4 = f & 63;
            cp_async16(&sW[0][hf][hhq][k4 * 4], Wsrc[hf] + hhq * HH + k4 * 4);
        }
        cp_commit();
    }

    float acc[ROWS];
#pragma unroll
    for (int r = 0; r < ROWS; ++r) acc[r] = 0.f;

    for (int t = 0; t < NT; ++t) {
        if (t + 1 < NT) {
            const int buf = (t + 1) & 1;
#pragma unroll
            for (int pass = 0; pass < 2; ++pass) {
                const int f  = tid + pass * 512;
                const int hf = f >> 9;
                const int hhq= (f >> 6) & 7;
                const int k4 = f & 63;
                cp_async16(&sW[buf][hf][hhq][k4 * 4],
                           Wsrc[hf] + ((t + 1) * THH + hhq) * HH + k4 * 4);
            }
            cp_commit();
            cp_wait<1>();
        } else {
            cp_wait<0>();
        }
        __syncthreads();

        const int buf = t & 1;
        const float* __restrict__ sWp = &sW[buf][half][0][k];
        const int hh0 = t * THH;
#pragma unroll
        for (int q = 0; q < THH; q += 4) {
            const float w0 = sWp[(q + 0) * HH];
            const float w1 = sWp[(q + 1) * HH];
            const float w2 = sWp[(q + 2) * HH];
            const float w3 = sWp[(q + 3) * HH];
#pragma unroll
            for (int r = 0; r < ROWS; ++r) {
                const float4 hv = *reinterpret_cast<const float4*>(&sh[r][hh0 + q]);
                acc[r] = fmaf(hv.x, w0, acc[r]);
                acc[r] = fmaf(hv.y, w1, acc[r]);
                acc[r] = fmaf(hv.z, w2, acc[r]);
                acc[r] = fmaf(hv.w, w3, acc[r]);
            }
        }
        __syncthreads();
    }

    if (half == 0) {
        const float bias = bh[k];
#pragma unroll
        for (int r = 0; r < ROWS; ++r)
            g_ht_h[(row0 + r) * HH + k] = __float2half(acc[r] + bias);
    } else {
        __half* htpT = reinterpret_cast<__half*>(g_htpT);
#pragma unroll
        for (int r = 0; r < ROWS; ++r) {
            const int row = row0 + r;
            const int b   = row >> 9;
            const int tp  = row & (SS - 1);
            htpT[(((size_t)b * H4 + (k >> 2)) * SS + tp) * 4 + (k & 3)] = __float2half(acc[r]);
        }
    }
}

// ---------------------------------------------------------------------------
// Stage 2 (fused): score map + partial output GEMM.
// grid = (NTILE=4 tp-tiles, 128 row-groups). Block: 16 t-rows x 128 tp.
// Phase A: warp w owns rows {2w,2w+1}; lane sweeps 4 tp (c-loop).
//          p -> g_p, smem psm, per-tile rowsums -> g_rsump.
// Phase B: thread k: 16-row x 128-tp partial GEMM vs h -> g_opart[tile].
//          FMA work hides under phase A's MUFU ceiling across blocks.
// ---------------------------------------------------------------------------
__global__ void __launch_bounds__(256)
score_kernel(const float* __restrict__ Wa,
             const float* __restrict__ ba,
             const float* __restrict__ hin)
{
    const int tile = blockIdx.x;            // 0..3
    const int bt0  = blockIdx.y * RG;       // 16 rows, one batch
    const int b    = bt0 >> 9;
    const int tid  = threadIdx.x;
    const int w    = tid >> 5;
    const int lane = tid & 31;

    __shared__ uint4 su[RG][H4];            // {ht01, ht23, wa01, wa23}  16KB
    __shared__ float psm[TPT][20];          // p transposed (pad 20 for banks) 10KB

    for (int e = tid; e < RG * H4; e += 256) {
        const int t  = e >> 6;
        const int h4 = e & 63;
        const uint2 ht4 = reinterpret_cast<const uint2*>(g_ht_h)[(bt0 + t) * (HH / 4) + h4];
        const float4 wa4 = reinterpret_cast<const float4*>(Wa)[h4];
        su[t][h4] = make_uint4(ht4.x, ht4.y,
                               h2u(__floats2half2_rn(wa4.x, wa4.y)),
                               h2u(__floats2half2_rn(wa4.z, wa4.w)));
    }
    __syncthreads();

    const float bav = ba[0];
    const int   r0  = 2 * w, r1 = 2 * w + 1;
    const __half2 z = __floats2half2_rn(0.f, 0.f);

    float ssum0 = 0.f, ssum1 = 0.f;

#pragma unroll 1
    for (int c = 0; c < 4; ++c) {
        const int tp = tile * TPT + c * 32 + lane;
        const uint2* hp = g_htpT + (size_t)b * H4 * SS + tp;

        float fa0 = 0.f, fa1 = 0.f;
        __half2 acc0 = z, acc1 = z;
#pragma unroll 1
        for (int hb = 0; hb < 16; ++hb) {
#pragma unroll
            for (int j = 0; j < 4; ++j) {
                const int h4 = hb * 4 + j;
                const uint2 x  = hp[(size_t)h4 * SS];
                const __half2 xa = u2h(x.x), xb = u2h(x.y);
                const uint4 u0 = su[r0][h4];
                const uint4 u1 = su[r1][h4];
                acc0 = __hfma2(u2h(u0.z), u2h(tanh2u(h2u(__hadd2(u2h(u0.x), xa)))), acc0);
                acc0 = __hfma2(u2h(u0.w), u2h(tanh2u(h2u(__hadd2(u2h(u0.y), xb)))), acc0);
                acc1 = __hfma2(u2h(u1.z), u2h(tanh2u(h2u(__hadd2(u2h(u1.x), xa)))), acc1);
                acc1 = __hfma2(u2h(u1.w), u2h(tanh2u(h2u(__hadd2(u2h(u1.y), xb)))), acc1);
            }
            const float2 f0 = __half22float2(acc0);
            const float2 f1 = __half22float2(acc1);
            fa0 += f0.x + f0.y;
            fa1 += f1.x + f1.y;
            acc0 = z; acc1 = z;
        }
        const float p0 = __expf(0.5f * tanh_fast(0.5f * (fa0 + bav)) + 0.5f);
        const float p1 = __expf(0.5f * tanh_fast(0.5f * (fa1 + bav)) + 0.5f);
        g_p[(size_t)(bt0 + r0) * SS + tp] = p0;
        g_p[(size_t)(bt0 + r1) * SS + tp] = p1;
        psm[c * 32 + lane][r0] = p0;
        psm[c * 32 + lane][r1] = p1;
        ssum0 += p0;
        ssum1 += p1;
    }

    // Per-tile row sums (deterministic: one writer per (tile,row)).
#pragma unroll
    for (int off = 16; off > 0; off >>= 1) {
        ssum0 += __shfl_xor_sync(0xffffffffu, ssum0, off);
        ssum1 += __shfl_xor_sync(0xffffffffu, ssum1, off);
    }
    if (lane == 0) {
        g_rsump[tile][bt0 + r0] = ssum0;
        g_rsump[tile][bt0 + r1] = ssum1;
    }
    __syncthreads();

    // Phase B: partial GEMM. thread = k; 128 tp x 16 rows.
    const int k = tid;
    float facc[RG];
#pragma unroll
    for (int r = 0; r < RG; ++r) facc[r] = 0.f;
    const float* hb = hin + ((size_t)b * SS + tile * TPT) * HH + k;
#pragma unroll 4
    for (int i = 0; i < TPT; ++i) {
        const float hv = hb[(size_t)i * HH];
        const float4 pA = *reinterpret_cast<const float4*>(&psm[i][0]);
        const float4 pB = *reinterpret_cast<const float4*>(&psm[i][4]);
        const float4 pC = *reinterpret_cast<const float4*>(&psm[i][8]);
        const float4 pD = *reinterpret_cast<const float4*>(&psm[i][12]);
        facc[0]  = fmaf(pA.x, hv, facc[0]);
        facc[1]  = fmaf(pA.y, hv, facc[1]);
        facc[2]  = fmaf(pA.z, hv, facc[2]);
        facc[3]  = fmaf(pA.w, hv, facc[3]);
        facc[4]  = fmaf(pB.x, hv, facc[4]);
        facc[5]  = fmaf(pB.y, hv, facc[5]);
        facc[6]  = fmaf(pB.z, hv, facc[6]);
        facc[7]  = fmaf(pB.w, hv, facc[7]);
        facc[8]  = fmaf(pC.x, hv, facc[8]);
        facc[9]  = fmaf(pC.y, hv, facc[9]);
        facc[10] = fmaf(pC.z, hv, facc[10]);
        facc[11] = fmaf(pC.w, hv, facc[11]);
        facc[12] = fmaf(pD.x, hv, facc[12]);
        facc[13] = fmaf(pD.y, hv, facc[13]);
        facc[14] = fmaf(pD.z, hv, facc[14]);
        facc[15] = fmaf(pD.w, hv, facc[15]);
    }
#pragma unroll
    for (int r = 0; r < RG; ++r)
        g_opart[tile][(size_t)(bt0 + r) * HH + k] = facc[r];
}

// ---------------------------------------------------------------------------
// Stage 3: finalize. Block = 4 t-rows: rinv from 4 partial rowsums (fixed
// order -> deterministic), out = sum of 4 partial GEMMs * rinv, wts = p*rinv.
// ---------------------------------------------------------------------------
__global__ void __launch_bounds__(256)
finalize_kernel(float* __restrict__ out,
                float* __restrict__ wts)
{
    const int bt0 = blockIdx.x * 4;
    const int tid = threadIdx.x;

    __shared__ float rinv[4];
    if (tid < 4) {
        float s = 0.f;
#pragma unroll
        for (int c = 0; c < NTILE; ++c) s += g_rsump[c][bt0 + tid];
        rinv[tid] = 1.0f / s;
    }
    __syncthreads();

    const int k = tid;
#pragma unroll
    for (int r = 0; r < 4; ++r) {
        const size_t idx = (size_t)(bt0 + r) * HH + k;
        float s = 0.f;
#pragma unroll
        for (int c = 0; c < NTILE; ++c) s += g_opart[c][idx];
        out[idx] = s * rinv[r];
    }

    if (wts) {
        for (int e = tid; e < 4 * SS; e += 256) {
            const int r  = e >> 9;
            const int tp = e & (SS - 1);
            wts[(size_t)(bt0 + r) * SS + tp] = g_p[(size_t)(bt0 + r) * SS + tp] * rinv[r];
        }
    }
}

// ---------------------------------------------------------------------------
extern "C" void kernel_launch(void* const* d_in, const int* in_sizes, int n_in,
                              void* d_out, int out_size)
{
    const float* h   = (const float*)d_in[0];
    const float* Wt  = (const float*)d_in[1];
    const float* Wtp = (const float*)d_in[2];
    const float* bh  = (const float*)d_in[3];
    const float* Wa  = (const float*)d_in[4];
    const float* ba  = (const float*)d_in[5];

    float* out = (float*)d_out;
    float* wts = nullptr;
    const int nOut = BB * SS * HH;   // 524288
    const int nW   = BB * SS * SS;   // 1048576
    if (out_size >= nOut + nW) wts = out + nOut;

    proj_kernel<<<BB * SS / 8, 512>>>(h, Wt, Wtp, bh);
    score_kernel<<<dim3(NTILE, BB * SS / RG), 256>>>(Wa, ba, h);
    finalize_kernel<<<BB * SS / 4, 256>>>(out, wts);
}

// round 9
// speedup vs baseline: 1.1454x; 1.1454x over previous
#include <cuda_runtime.h>
#include <cuda_fp16.h>
#include <mma.h>
using namespace nvcuda;

#define BB 4
#define SS 512
#define HH 256
#define H4 (HH / 4)        // 64 groups of 4 h-elements

// Scratch (allocation-free rule -> __device__ globals)
__device__ __half g_h16 [BB * SS * HH];      // h in fp16
__device__ __half g_wt16 [HH * HH];          // Wt in fp16
__device__ __half g_wtp16[HH * HH];          // Wtp in fp16
__device__ __half g_ht_h[BB * SS * HH];      // [bt][h]  ht + b_h, half
__device__ uint2  g_htpT[BB * H4 * SS];      // [b][h4][tp] packed halves of htp
__device__ float  g_p[BB * SS * SS];         // unnormalized exp(sigmoid(score))

__device__ __forceinline__ float tanh_fast(float x) {
    float y; asm("tanh.approx.f32 %0, %1;" : "=f"(y) : "f"(x)); return y;
}
__device__ __forceinline__ unsigned tanh2u(unsigned x) {
    unsigned y; asm("tanh.approx.f16x2 %0, %1;" : "=r"(y) : "r"(x)); return y;
}
__device__ __forceinline__ __half2 u2h(unsigned x) { return *reinterpret_cast<__half2*>(&x); }
__device__ __forceinline__ unsigned h2u(__half2 x) { return *reinterpret_cast<unsigned*>(&x); }

// ---------------------------------------------------------------------------
// Stage 0: fp32 -> fp16 conversion of h, Wt, Wtp (vectorized).
// ---------------------------------------------------------------------------
__global__ void __launch_bounds__(256)
convert_kernel(const float* __restrict__ h,
               const float* __restrict__ Wt,
               const float* __restrict__ Wtp)
{
    const int g      = blockIdx.x * blockDim.x + threadIdx.x;
    const int stride = gridDim.x * blockDim.x;

    const int nH = BB * SS * HH / 4;   // float4 count for h
    const int nW = HH * HH / 4;        // float4 count per W

    uint2* h16  = reinterpret_cast<uint2*>(g_h16);
    uint2* wt16 = reinterpret_cast<uint2*>(g_wt16);
    uint2* wp16 = reinterpret_cast<uint2*>(g_wtp16);

    for (int i = g; i < nH; i += stride) {
        const float4 v = reinterpret_cast<const float4*>(h)[i];
        uint2 o;
        o.x = h2u(__floats2half2_rn(v.x, v.y));
        o.y = h2u(__floats2half2_rn(v.z, v.w));
        h16[i] = o;
    }
    for (int i = g; i < nW; i += stride) {
        const float4 a = reinterpret_cast<const float4*>(Wt)[i];
        const float4 b = reinterpret_cast<const float4*>(Wtp)[i];
        uint2 oa, ob;
        oa.x = h2u(__floats2half2_rn(a.x, a.y));
        oa.y = h2u(__floats2half2_rn(a.z, a.w));
        ob.x = h2u(__floats2half2_rn(b.x, b.y));
        ob.y = h2u(__floats2half2_rn(b.z, b.w));
        wt16[i] = oa;
        wp16[i] = ob;
    }
}

// ---------------------------------------------------------------------------
// Stage 1: projections on tensor cores (wmma fp16, fp32 accumulate).
// Block: 64x64 output tile, 8 warps (4x2), warp = 16x32 (two 16x16 n-frags).
// grid = (M/64=32, N/64=4, 2); z selects Wt (->g_ht_h) vs Wtp (->g_htpT).
// ---------------------------------------------------------------------------
__global__ void __launch_bounds__(256)
proj_wmma_kernel(const float* __restrict__ bh)
{
    const int mt   = blockIdx.x;        // 0..31
    const int nt   = blockIdx.y;        // 0..3
    const int wsel = blockIdx.z;        // 0: Wt, 1: Wtp
    const __half* __restrict__ A = g_h16;
    const __half* __restrict__ B = wsel ? g_wtp16 : g_wt16;

    const int warp = threadIdx.x >> 5;
    const int wm   = warp >> 1;         // 0..3
    const int wn   = warp & 1;          // 0..1
    const int row0 = mt * 64 + wm * 16;
    const int col0 = nt * 64 + wn * 32;

    wmma::fragment<wmma::accumulator, 16, 16, 16, float> c0, c1;
    wmma::fill_fragment(c0, 0.f);
    wmma::fill_fragment(c1, 0.f);

#pragma unroll 4
    for (int k = 0; k < HH; k += 16) {
        wmma::fragment<wmma::matrix_a, 16, 16, 16, __half, wmma::row_major> a;
        wmma::fragment<wmma::matrix_b, 16, 16, 16, __half, wmma::row_major> b0, b1;
        wmma::load_matrix_sync(a,  A + (size_t)row0 * HH + k, HH);
        wmma::load_matrix_sync(b0, B + (size_t)k * HH + col0,      HH);
        wmma::load_matrix_sync(b1, B + (size_t)k * HH + col0 + 16, HH);
        wmma::mma_sync(c0, a, b0, c0);
        wmma::mma_sync(c1, a, b1, c1);
    }

    __shared__ float cs[64][68];        // pad 68 (mult of 4) against conflicts
    wmma::store_matrix_sync(&cs[wm * 16][wn * 32],      c0, 68, wmma::mem_row_major);
    wmma::store_matrix_sync(&cs[wm * 16][wn * 32 + 16], c1, 68, wmma::mem_row_major);
    __syncthreads();

    const int tid = threadIdx.x;
    if (wsel == 0) {
        for (int e = tid; e < 64 * 64; e += 256) {
            const int r = e >> 6, c = e & 63;
            const int row = mt * 64 + r;
            const int col = nt * 64 + c;
            g_ht_h[(size_t)row * HH + col] = __float2half(cs[r][c] + bh[col]);
        }
    } else {
        __half* htpT = reinterpret_cast<__half*>(g_htpT);
        for (int e = tid; e < 64 * 64; e += 256) {
            const int r = e >> 6, c = e & 63;
            const int row = mt * 64 + r;          // = bt
            const int col = nt * 64 + c;
            const int b   = row >> 9;
            const int tp  = row & (SS - 1);
            htpT[(((size_t)b * H4 + (col >> 2)) * SS + tp) * 4 + (col & 3)] =
                __float2half(cs[r][c]);
        }
    }
}

// ---------------------------------------------------------------------------
// Stage 2: pure (t, tp) score map, no normalization. (R4/R6 version)
//   p[bt][tp] = exp(sigmoid(Wa . tanh(ht[t] + htp[tp]) + ba))
// ---------------------------------------------------------------------------
__global__ void __launch_bounds__(256)
score_kernel(const float* __restrict__ Wa,
             const float* __restrict__ ba)
{
    const int bt0 = blockIdx.y * 16;        // 16 rows, same batch (16 | 512)
    const int b   = bt0 >> 9;
    const int tid = threadIdx.x;
    const int w   = tid >> 5;
    const int lane= tid & 31;

    __shared__ uint4 su[16][H4];            // {ht01, ht23, wa01, wa23}  16KB

    for (int e = tid; e < 16 * H4; e += 256) {
        const int t  = e >> 6;
        const int h4 = e & 63;
        const uint2 ht4 = reinterpret_cast<const uint2*>(g_ht_h)[(bt0 + t) * (HH / 4) + h4];
        const float4 wa4 = reinterpret_cast<const float4*>(Wa)[h4];
        su[t][h4] = make_uint4(ht4.x, ht4.y,
                               h2u(__floats2half2_rn(wa4.x, wa4.y)),
                               h2u(__floats2half2_rn(wa4.z, wa4.w)));
    }
    __syncthreads();

    const float bav = ba[0];
    const int   tp  = blockIdx.x * 32 + lane;
    const int   r0  = 2 * w, r1 = 2 * w + 1;
    const uint2* hp = g_htpT + (size_t)b * H4 * SS + tp;

    float fa0 = 0.f, fa1 = 0.f;
    __half2 z = __floats2half2_rn(0.f, 0.f);
    __half2 acc0 = z, acc1 = z;

#pragma unroll 1
    for (int hb = 0; hb < 16; ++hb) {       // fold to fp32 every 4 h4
#pragma unroll
        for (int j = 0; j < 4; ++j) {
            const int h4 = hb * 4 + j;
            const uint2 x  = hp[(size_t)h4 * SS];
            const __half2 xa = u2h(x.x), xb = u2h(x.y);
            const uint4 u0 = su[r0][h4];
            const uint4 u1 = su[r1][h4];
            acc0 = __hfma2(u2h(u0.z), u2h(tanh2u(h2u(__hadd2(u2h(u0.x), xa)))), acc0);
            acc0 = __hfma2(u2h(u0.w), u2h(tanh2u(h2u(__hadd2(u2h(u0.y), xb)))), acc0);
            acc1 = __hfma2(u2h(u1.z), u2h(tanh2u(h2u(__hadd2(u2h(u1.x), xa)))), acc1);
            acc1 = __hfma2(u2h(u1.w), u2h(tanh2u(h2u(__hadd2(u2h(u1.y), xb)))), acc1);
        }
        const float2 f0 = __half22float2(acc0);
        const float2 f1 = __half22float2(acc1);
        fa0 += f0.x + f0.y;
        fa1 += f1.x + f1.y;
        acc0 = z; acc1 = z;
    }

    const float s0 = fa0 + bav;
    const float s1 = fa1 + bav;
    const float p0 = __expf(0.5f * tanh_fast(0.5f * s0) + 0.5f);
    const float p1 = __expf(0.5f * tanh_fast(0.5f * s1) + 0.5f);
    g_p[(size_t)(bt0 + r0) * SS + tp] = p0;
    g_p[(size_t)(bt0 + r1) * SS + tp] = p1;
}

// ---------------------------------------------------------------------------
// Stage 3: rowsum + normalize + output GEMM, 512 threads. (R5/R6 version)
// ---------------------------------------------------------------------------
__global__ void __launch_bounds__(512)
out_kernel(const float* __restrict__ hin,
           float* __restrict__ out,
           float* __restrict__ wts)
{
    const int bt0 = blockIdx.x * 8;
    const int b   = bt0 >> 9;
    const int tid = threadIdx.x;
    const int w   = tid >> 5;
    const int lane= tid & 31;
    const int seg = tid >> 8;           // 0 or 1 (tp half)
    const int k   = tid & 255;

    __shared__ float pT[SS][8];             // transposed p (unnormalized)  16KB
    __shared__ float part[8][HH];           // seg-1 partial sums           8KB
    __shared__ float rinv[8];

    // Load p coalesced, store transposed.
    for (int e = tid; e < 8 * SS; e += 512) {
        const int t  = e >> 9;
        const int tp = e & (SS - 1);
        pT[tp][t] = g_p[(size_t)(bt0 + t) * SS + tp];
    }
    __syncthreads();

    // Rowsum: warps 0..7 own rows 0..7.
    if (w < 8) {
        float s = 0.f;
        for (int tp = lane; tp < SS; tp += 32) s += pT[tp][w];
#pragma unroll
        for (int off = 16; off > 0; off >>= 1)
            s += __shfl_xor_sync(0xffffffffu, s, off);
        if (lane == 0) rinv[w] = 1.0f / s;
    }
    __syncthreads();

    // Normalized weights output.
    if (wts) {
        for (int e = tid; e < 8 * SS; e += 512) {
            const int t  = e >> 9;
            const int tp = e & (SS - 1);
            wts[(size_t)(bt0 + t) * SS + tp] = pT[tp][t] * rinv[t];
        }
    }

    // GEMM with unnormalized p over this segment's tp range.
    float facc[8];
#pragma unroll
    for (int r = 0; r < 8; ++r) facc[r] = 0.f;
    const float* hb = hin + (size_t)b * SS * HH + k;
    const int tp0 = seg * 256;
#pragma unroll 4
    for (int i = 0; i < 256; ++i) {
        const int tp = tp0 + i;
        const float hv = hb[(size_t)tp * HH];
        const float4 wA = *reinterpret_cast<const float4*>(&pT[tp][0]);
        const float4 wB = *reinterpret_cast<const float4*>(&pT[tp][4]);
        facc[0] = fmaf(wA.x, hv, facc[0]);
        facc[1] = fmaf(wA.y, hv, facc[1]);
        facc[2] = fmaf(wA.z, hv, facc[2]);
        facc[3] = fmaf(wA.w, hv, facc[3]);
        facc[4] = fmaf(wB.x, hv, facc[4]);
        facc[5] = fmaf(wB.y, hv, facc[5]);
        facc[6] = fmaf(wB.z, hv, facc[6]);
        facc[7] = fmaf(wB.w, hv, facc[7]);
    }

    if (seg == 1) {
#pragma unroll
        for (int r = 0; r < 8; ++r) part[r][k] = facc[r];
    }
    __syncthreads();
    if (seg == 0) {
#pragma unroll
        for (int r = 0; r < 8; ++r)
            out[(size_t)(bt0 + r) * HH + k] = (facc[r] + part[r][k]) * rinv[r];
    }
}

// ---------------------------------------------------------------------------
extern "C" void kernel_launch(void* const* d_in, const int* in_sizes, int n_in,
                              void* d_out, int out_size)
{
    const float* h   = (const float*)d_in[0];
    const float* Wt  = (const float*)d_in[1];
    const float* Wtp = (const float*)d_in[2];
    const float* bh  = (const float*)d_in[3];
    const float* Wa  = (const float*)d_in[4];
    const float* ba  = (const float*)d_in[5];

    float* out = (float*)d_out;
    float* wts = nullptr;
    const int nOut = BB * SS * HH;   // 524288
    const int nW   = BB * SS * SS;   // 1048576
    if (out_size >= nOut + nW) wts = out + nOut;

    convert_kernel<<<256, 256>>>(h, Wt, Wtp);
    proj_wmma_kernel<<<dim3(32, 4, 2), 256>>>(bh);
    score_kernel<<<dim3(SS / 32, BB * SS / 16), 256>>>(Wa, ba);
    out_kernel<<<BB * SS / 8, 512>>>(h, out, wts);
}

// round 11
// speedup vs baseline: 1.2017x; 1.0492x over previous
#include <cuda_runtime.h>
#include <cuda_fp16.h>
#include <mma.h>
using namespace nvcuda;

#define BB 4
#define SS 512
#define HH 256
#define H4 (HH / 4)        // 64 groups of 4 h-elements

// Scratch (allocation-free rule -> __device__ globals)
__device__ __half g_h16 [BB * SS * HH];      // h in fp16
__device__ __half g_wt16 [HH * HH];          // Wt in fp16
__device__ __half g_wtp16[HH * HH];          // Wtp in fp16
__device__ __half g_ht_h[BB * SS * HH];      // [bt][h]  ht + b_h, half
__device__ uint2  g_htpT[BB * H4 * SS];      // [b][h4][tp] packed halves of htp
__device__ float  g_p[BB * SS * SS];         // unnormalized exp(sigmoid(score))
__device__ __half g_p16[BB * SS * SS];       // same, fp16 (wmma A operand)
__device__ float  g_rinv[BB * SS];           // 1 / rowsum

__device__ __forceinline__ float tanh_fast(float x) {
    float y; asm("tanh.approx.f32 %0, %1;" : "=f"(y) : "f"(x)); return y;
}
__device__ __forceinline__ unsigned tanh2u(unsigned x) {
    unsigned y; asm("tanh.approx.f16x2 %0, %1;" : "=r"(y) : "r"(x)); return y;
}
__device__ __forceinline__ __half2 u2h(unsigned x) { return *reinterpret_cast<__half2*>(&x); }
__device__ __forceinline__ unsigned h2u(__half2 x) { return *reinterpret_cast<unsigned*>(&x); }

// ---------------------------------------------------------------------------
// Stage 0: fp32 -> fp16 conversion of h, Wt, Wtp (vectorized).
// ---------------------------------------------------------------------------
__global__ void __launch_bounds__(256)
convert_kernel(const float* __restrict__ h,
               const float* __restrict__ Wt,
               const float* __restrict__ Wtp)
{
    const int g      = blockIdx.x * blockDim.x + threadIdx.x;
    const int stride = gridDim.x * blockDim.x;

    const int nH = BB * SS * HH / 4;
    const int nW = HH * HH / 4;

    uint2* h16  = reinterpret_cast<uint2*>(g_h16);
    uint2* wt16 = reinterpret_cast<uint2*>(g_wt16);
    uint2* wp16 = reinterpret_cast<uint2*>(g_wtp16);

    for (int i = g; i < nH; i += stride) {
        const float4 v = reinterpret_cast<const float4*>(h)[i];
        uint2 o;
        o.x = h2u(__floats2half2_rn(v.x, v.y));
        o.y = h2u(__floats2half2_rn(v.z, v.w));
        h16[i] = o;
    }
    for (int i = g; i < nW; i += stride) {
        const float4 a = reinterpret_cast<const float4*>(Wt)[i];
        const float4 b = reinterpret_cast<const float4*>(Wtp)[i];
        uint2 oa, ob;
        oa.x = h2u(__floats2half2_rn(a.x, a.y));
        oa.y = h2u(__floats2half2_rn(a.z, a.w));
        ob.x = h2u(__floats2half2_rn(b.x, b.y));
        ob.y = h2u(__floats2half2_rn(b.z, b.w));
        wt16[i] = oa;
        wp16[i] = ob;
    }
}

// ---------------------------------------------------------------------------
// Stage 1: projections on tensor cores (wmma fp16, fp32 accumulate).
// ---------------------------------------------------------------------------
__global__ void __launch_bounds__(256)
proj_wmma_kernel(const float* __restrict__ bh)
{
    const int mt   = blockIdx.x;        // 0..31
    const int nt   = blockIdx.y;        // 0..3
    const int wsel = blockIdx.z;        // 0: Wt, 1: Wtp
    const __half* __restrict__ A = g_h16;
    const __half* __restrict__ B = wsel ? g_wtp16 : g_wt16;

    const int warp = threadIdx.x >> 5;
    const int wm   = warp >> 1;
    const int wn   = warp & 1;
    const int row0 = mt * 64 + wm * 16;
    const int col0 = nt * 64 + wn * 32;

    wmma::fragment<wmma::accumulator, 16, 16, 16, float> c0, c1;
    wmma::fill_fragment(c0, 0.f);
    wmma::fill_fragment(c1, 0.f);

#pragma unroll 4
    for (int k = 0; k < HH; k += 16) {
        wmma::fragment<wmma::matrix_a, 16, 16, 16, __half, wmma::row_major> a;
        wmma::fragment<wmma::matrix_b, 16, 16, 16, __half, wmma::row_major> b0, b1;
        wmma::load_matrix_sync(a,  A + (size_t)row0 * HH + k, HH);
        wmma::load_matrix_sync(b0, B + (size_t)k * HH + col0,      HH);
        wmma::load_matrix_sync(b1, B + (size_t)k * HH + col0 + 16, HH);
        wmma::mma_sync(c0, a, b0, c0);
        wmma::mma_sync(c1, a, b1, c1);
    }

    __shared__ float cs[64][68];
    wmma::store_matrix_sync(&cs[wm * 16][wn * 32],      c0, 68, wmma::mem_row_major);
    wmma::store_matrix_sync(&cs[wm * 16][wn * 32 + 16], c1, 68, wmma::mem_row_major);
    __syncthreads();

    const int tid = threadIdx.x;
    if (wsel == 0) {
        for (int e = tid; e < 64 * 64; e += 256) {
            const int r = e >> 6, c = e & 63;
            const int row = mt * 64 + r;
            const int col = nt * 64 + c;
            g_ht_h[(size_t)row * HH + col] = __float2half(cs[r][c] + bh[col]);
        }
    } else {
        __half* htpT = reinterpret_cast<__half*>(g_htpT);
        for (int e = tid; e < 64 * 64; e += 256) {
            const int r = e >> 6, c = e & 63;
            const int row = mt * 64 + r;          // = bt
            const int col = nt * 64 + c;
            const int b   = row >> 9;
            const int tp  = row & (SS - 1);
            htpT[(((size_t)b * H4 + (col >> 2)) * SS + tp) * 4 + (col & 3)] =
                __float2half(cs[r][c]);
        }
    }
}

// ---------------------------------------------------------------------------
// Stage 2: score map; writes p in fp32 (weights path) and fp16 (GEMM A).
// ---------------------------------------------------------------------------
__global__ void __launch_bounds__(256)
score_kernel(const float* __restrict__ Wa,
             const float* __restrict__ ba)
{
    const int bt0 = blockIdx.y * 16;
    const int b   = bt0 >> 9;
    const int tid = threadIdx.x;
    const int w   = tid >> 5;
    const int lane= tid & 31;

    __shared__ uint4 su[16][H4];

    for (int e = tid; e < 16 * H4; e += 256) {
        const int t  = e >> 6;
        const int h4 = e & 63;
        const uint2 ht4 = reinterpret_cast<const uint2*>(g_ht_h)[(bt0 + t) * (HH / 4) + h4];
        const float4 wa4 = reinterpret_cast<const float4*>(Wa)[h4];
        su[t][h4] = make_uint4(ht4.x, ht4.y,
                               h2u(__floats2half2_rn(wa4.x, wa4.y)),
                               h2u(__floats2half2_rn(wa4.z, wa4.w)));
    }
    __syncthreads();

    const float bav = ba[0];
    const int   tp  = blockIdx.x * 32 + lane;
    const int   r0  = 2 * w, r1 = 2 * w + 1;
    const uint2* hp = g_htpT + (size_t)b * H4 * SS + tp;

    float fa0 = 0.f, fa1 = 0.f;
    __half2 z = __floats2half2_rn(0.f, 0.f);
    __half2 acc0 = z, acc1 = z;

#pragma unroll 1
    for (int hb = 0; hb < 16; ++hb) {
#pragma unroll
        for (int j = 0; j < 4; ++j) {
            const int h4 = hb * 4 + j;
            const uint2 x  = hp[(size_t)h4 * SS];
            const __half2 xa = u2h(x.x), xb = u2h(x.y);
            const uint4 u0 = su[r0][h4];
            const uint4 u1 = su[r1][h4];
            acc0 = __hfma2(u2h(u0.z), u2h(tanh2u(h2u(__hadd2(u2h(u0.x), xa)))), acc0);
            acc0 = __hfma2(u2h(u0.w), u2h(tanh2u(h2u(__hadd2(u2h(u0.y), xb)))), acc0);
            acc1 = __hfma2(u2h(u1.z), u2h(tanh2u(h2u(__hadd2(u2h(u1.x), xa)))), acc1);
            acc1 = __hfma2(u2h(u1.w), u2h(tanh2u(h2u(__hadd2(u2h(u1.y), xb)))), acc1);
        }
        const float2 f0 = __half22float2(acc0);
        const float2 f1 = __half22float2(acc1);
        fa0 += f0.x + f0.y;
        fa1 += f1.x + f1.y;
        acc0 = z; acc1 = z;
    }

    const float s0 = fa0 + bav;
    const float s1 = fa1 + bav;
    const float p0 = __expf(0.5f * tanh_fast(0.5f * s0) + 0.5f);
    const float p1 = __expf(0.5f * tanh_fast(0.5f * s1) + 0.5f);
    g_p  [(size_t)(bt0 + r0) * SS + tp] = p0;
    g_p  [(size_t)(bt0 + r1) * SS + tp] = p1;
    g_p16[(size_t)(bt0 + r0) * SS + tp] = __float2half(p0);
    g_p16[(size_t)(bt0 + r1) * SS + tp] = __float2half(p1);
}

// ---------------------------------------------------------------------------
// Stage 3a: row sums -> g_rinv, and normalized weights output.
// Block = 8 rows; warp w owns row bt0+w.
// ---------------------------------------------------------------------------
__global__ void __launch_bounds__(256)
rowsum_wts_kernel(float* __restrict__ wts)
{
    const int bt0 = blockIdx.x * 8;
    const int tid = threadIdx.x;
    const int w   = tid >> 5;
    const int lane= tid & 31;

    __shared__ float rinv[8];

    {
        const float4* pr = reinterpret_cast<const float4*>(g_p + (size_t)(bt0 + w) * SS);
        float s = 0.f;
#pragma unroll
        for (int j = 0; j < 4; ++j) {
            const float4 v = pr[lane + 32 * j];
            s += (v.x + v.y) + (v.z + v.w);
        }
#pragma unroll
        for (int off = 16; off > 0; off >>= 1)
            s += __shfl_xor_sync(0xffffffffu, s, off);
        if (lane == 0) rinv[w] = 1.0f / s;
    }
    __syncthreads();

    if (tid < 8) g_rinv[bt0 + tid] = rinv[tid];

    if (wts) {
        const float4* ps = reinterpret_cast<const float4*>(g_p);
        float4*       wd = reinterpret_cast<float4*>(wts);
#pragma unroll
        for (int e = tid; e < 8 * (SS / 4); e += 256) {
            const int r  = e >> 7;              // row within block
            const float sc = rinv[r];
            float4 v = ps[(size_t)(bt0 + r) * (SS / 4) + (e & 127)];
            v.x *= sc; v.y *= sc; v.z *= sc; v.w *= sc;
            wd[(size_t)(bt0 + r) * (SS / 4) + (e & 127)] = v;
        }
    }
}

// ---------------------------------------------------------------------------
// Stage 3b: output GEMM on tensor cores.
// out[b][t][k] = rinv[bt] * sum_tp p16[bt][tp] * h16[b][tp][k]
// Block: 64x64 tile, 8 warps; grid (512/64=8, 256/64=4, BB).
// ---------------------------------------------------------------------------
__global__ void __launch_bounds__(256)
out_wmma_kernel(float* __restrict__ out)
{
    const int mt = blockIdx.x;          // 0..7  (t tile)
    const int nt = blockIdx.y;          // 0..3  (k tile)
    const int b  = blockIdx.z;          // batch

    const __half* __restrict__ A = g_p16 + (size_t)b * SS * SS;   // [t][tp]
    const __half* __restrict__ B = g_h16 + (size_t)b * SS * HH;   // [tp][k]

    const int warp = threadIdx.x >> 5;
    const int wm   = warp >> 1;
    const int wn   = warp & 1;
    const int row0 = mt * 64 + wm * 16;
    const int col0 = nt * 64 + wn * 32;

    wmma::fragment<wmma::accumulator, 16, 16, 16, float> c0, c1;
    wmma::fill_fragment(c0, 0.f);
    wmma::fill_fragment(c1, 0.f);

#pragma unroll 4
    for (int k = 0; k < SS; k += 16) {
        wmma::fragment<wmma::matrix_a, 16, 16, 16, __half, wmma::row_major> a;
        wmma::fragment<wmma::matrix_b, 16, 16, 16, __half, wmma::row_major> b0, b1;
        wmma::load_matrix_sync(a,  A + (size_t)row0 * SS + k, SS);
        wmma::load_matrix_sync(b0, B + (size_t)k * HH + col0,      HH);
        wmma::load_matrix_sync(b1, B + (size_t)k * HH + col0 + 16, HH);
        wmma::mma_sync(c0, a, b0, c0);
        wmma::mma_sync(c1, a, b1, c1);
    }

    __shared__ float cs[64][68];
    wmma::store_matrix_sync(&cs[wm * 16][wn * 32],      c0, 68, wmma::mem_row_major);
    wmma::store_matrix_sync(&cs[wm * 16][wn * 32 + 16], c1, 68, wmma::mem_row_major);
    __syncthreads();

    const int tid = threadIdx.x;
    for (int e = tid; e < 64 * 64; e += 256) {
        const int r = e >> 6, c = e & 63;
        const int bt  = b * SS + mt * 64 + r;
        const int col = nt * 64 + c;
        out[(size_t)bt * HH + col] = cs[r][c] * g_rinv[bt];
    }
}

// ---------------------------------------------------------------------------
extern "C" void kernel_launch(void* const* d_in, const int* in_sizes, int n_in,
                              void* d_out, int out_size)
{
    const float* h   = (const float*)d_in[0];
    const float* Wt  = (const float*)d_in[1];
    const float* Wtp = (const float*)d_in[2];
    const float* bh  = (const float*)d_in[3];
    const float* Wa  = (const float*)d_in[4];
    const float* ba  = (const float*)d_in[5];

    float* out = (float*)d_out;
    float* wts = nullptr;
    const int nOut = BB * SS * HH;   // 524288
    const int nW   = BB * SS * SS;   // 1048576
    if (out_size >= nOut + nW) wts = out + nOut;

    convert_kernel<<<256, 256>>>(h, Wt, Wtp);
    proj_wmma_kernel<<<dim3(32, 4, 2), 256>>>(bh);
    score_kernel<<<dim3(SS / 32, BB * SS / 16), 256>>>(Wa, ba);
    rowsum_wts_kernel<<<BB * SS / 8, 256>>>(wts);
    out_wmma_kernel<<<dim3(8, 4, BB), 256>>>(out);
}

// round 12
// speedup vs baseline: 1.2303x; 1.0238x over previous
#include <cuda_runtime.h>
#include <cuda_fp16.h>
#include <mma.h>
using namespace nvcuda;

#define BB 4
#define SS 512
#define HH 256
#define H4 (HH / 4)        // 64 groups of 4 h-elements

// Scratch (allocation-free rule -> __device__ globals)
__device__ __half g_h16 [BB * SS * HH];      // h in fp16
__device__ __half g_wt16 [HH * HH];          // Wt in fp16
__device__ __half g_wtp16[HH * HH];          // Wtp in fp16
__device__ __half g_ht_h[BB * SS * HH];      // [bt][h]  ht + b_h, half
__device__ uint2  g_htpT[BB * H4 * SS];      // [b][h4][tp] packed halves of htp
__device__ __half g_p16[BB * SS * SS];       // unnormalized exp(sigmoid(score)), fp16

__device__ __forceinline__ float tanh_fast(float x) {
    float y; asm("tanh.approx.f32 %0, %1;" : "=f"(y) : "f"(x)); return y;
}
__device__ __forceinline__ unsigned tanh2u(unsigned x) {
    unsigned y; asm("tanh.approx.f16x2 %0, %1;" : "=r"(y) : "r"(x)); return y;
}
__device__ __forceinline__ __half2 u2h(unsigned x) { return *reinterpret_cast<__half2*>(&x); }
__device__ __forceinline__ unsigned h2u(__half2 x) { return *reinterpret_cast<unsigned*>(&x); }

// ---------------------------------------------------------------------------
// Stage 0: fp32 -> fp16 conversion of h, Wt, Wtp (vectorized).
// ---------------------------------------------------------------------------
__global__ void __launch_bounds__(256)
convert_kernel(const float* __restrict__ h,
               const float* __restrict__ Wt,
               const float* __restrict__ Wtp)
{
    const int g      = blockIdx.x * blockDim.x + threadIdx.x;
    const int stride = gridDim.x * blockDim.x;

    const int nH = BB * SS * HH / 4;
    const int nW = HH * HH / 4;

    uint2* h16  = reinterpret_cast<uint2*>(g_h16);
    uint2* wt16 = reinterpret_cast<uint2*>(g_wt16);
    uint2* wp16 = reinterpret_cast<uint2*>(g_wtp16);

    for (int i = g; i < nH; i += stride) {
        const float4 v = reinterpret_cast<const float4*>(h)[i];
        uint2 o;
        o.x = h2u(__floats2half2_rn(v.x, v.y));
        o.y = h2u(__floats2half2_rn(v.z, v.w));
        h16[i] = o;
    }
    for (int i = g; i < nW; i += stride) {
        const float4 a = reinterpret_cast<const float4*>(Wt)[i];
        const float4 b = reinterpret_cast<const float4*>(Wtp)[i];
        uint2 oa, ob;
        oa.x = h2u(__floats2half2_rn(a.x, a.y));
        oa.y = h2u(__floats2half2_rn(a.z, a.w));
        ob.x = h2u(__floats2half2_rn(b.x, b.y));
        ob.y = h2u(__floats2half2_rn(b.z, b.w));
        wt16[i] = oa;
        wp16[i] = ob;
    }
}

// ---------------------------------------------------------------------------
// Stage 1: projections on tensor cores (wmma fp16, fp32 accumulate).
// ---------------------------------------------------------------------------
__global__ void __launch_bounds__(256)
proj_wmma_kernel(const float* __restrict__ bh)
{
    const int mt   = blockIdx.x;        // 0..31
    const int nt   = blockIdx.y;        // 0..3
    const int wsel = blockIdx.z;        // 0: Wt, 1: Wtp
    const __half* __restrict__ A = g_h16;
    const __half* __restrict__ B = wsel ? g_wtp16 : g_wt16;

    const int warp = threadIdx.x >> 5;
    const int wm   = warp >> 1;
    const int wn   = warp & 1;
    const int row0 = mt * 64 + wm * 16;
    const int col0 = nt * 64 + wn * 32;

    wmma::fragment<wmma::accumulator, 16, 16, 16, float> c0, c1;
    wmma::fill_fragment(c0, 0.f);
    wmma::fill_fragment(c1, 0.f);

#pragma unroll 4
    for (int k = 0; k < HH; k += 16) {
        wmma::fragment<wmma::matrix_a, 16, 16, 16, __half, wmma::row_major> a;
        wmma::fragment<wmma::matrix_b, 16, 16, 16, __half, wmma::row_major> b0, b1;
        wmma::load_matrix_sync(a,  A + (size_t)row0 * HH + k, HH);
        wmma::load_matrix_sync(b0, B + (size_t)k * HH + col0,      HH);
        wmma::load_matrix_sync(b1, B + (size_t)k * HH + col0 + 16, HH);
        wmma::mma_sync(c0, a, b0, c0);
        wmma::mma_sync(c1, a, b1, c1);
    }

    __shared__ float cs[64][68];
    wmma::store_matrix_sync(&cs[wm * 16][wn * 32],      c0, 68, wmma::mem_row_major);
    wmma::store_matrix_sync(&cs[wm * 16][wn * 32 + 16], c1, 68, wmma::mem_row_major);
    __syncthreads();

    const int tid = threadIdx.x;
    if (wsel == 0) {
        for (int e = tid; e < 64 * 64; e += 256) {
            const int r = e >> 6, c = e & 63;
            const int row = mt * 64 + r;
            const int col = nt * 64 + c;
            g_ht_h[(size_t)row * HH + col] = __float2half(cs[r][c] + bh[col]);
        }
    } else {
        __half* htpT = reinterpret_cast<__half*>(g_htpT);
        for (int e = tid; e < 64 * 64; e += 256) {
            const int r = e >> 6, c = e & 63;
            const int row = mt * 64 + r;          // = bt
            const int col = nt * 64 + c;
            const int b   = row >> 9;
            const int tp  = row & (SS - 1);
            htpT[(((size_t)b * H4 + (col >> 2)) * SS + tp) * 4 + (col & 3)] =
                __float2half(cs[r][c]);
        }
    }
}

// ---------------------------------------------------------------------------
// Stage 2: score map v2. 32 rows/block (4 rows/warp), grid (16, 64).
// Each htp load now feeds 4 rows (2x LDG reduction vs v1).
//   p16[bt][tp] = fp16(exp(sigmoid(Wa . tanh(ht[t] + htp[tp]) + ba)))
// ---------------------------------------------------------------------------
__global__ void __launch_bounds__(256)
score_kernel(const float* __restrict__ Wa,
             const float* __restrict__ ba)
{
    const int bt0 = blockIdx.y * 32;        // 32 rows, one batch (32 | 512)
    const int b   = bt0 >> 9;
    const int tid = threadIdx.x;
    const int w   = tid >> 5;
    const int lane= tid & 31;

    __shared__ uint4 su[32][H4];            // {ht01, ht23, wa01, wa23}  32KB

    for (int e = tid; e < 32 * H4; e += 256) {
        const int t  = e >> 6;
        const int h4 = e & 63;
        const uint2 ht4 = reinterpret_cast<const uint2*>(g_ht_h)[(bt0 + t) * (HH / 4) + h4];
        const float4 wa4 = reinterpret_cast<const float4*>(Wa)[h4];
        su[t][h4] = make_uint4(ht4.x, ht4.y,
                               h2u(__floats2half2_rn(wa4.x, wa4.y)),
                               h2u(__floats2half2_rn(wa4.z, wa4.w)));
    }
    __syncthreads();

    const float bav = ba[0];
    const int   tp  = blockIdx.x * 32 + lane;
    const int   r0  = 4 * w;                // warp owns rows r0..r0+3
    const uint2* hp = g_htpT + (size_t)b * H4 * SS + tp;
    const uint4* s0 = su[r0 + 0];
    const uint4* s1 = su[r0 + 1];
    const uint4* s2 = su[r0 + 2];
    const uint4* s3 = su[r0 + 3];

    const __half2 z = __floats2half2_rn(0.f, 0.f);
    float   fa[4]  = {0.f, 0.f, 0.f, 0.f};
    __half2 acc[4] = {z, z, z, z};

#pragma unroll 1
    for (int hb = 0; hb < 16; ++hb) {       // fold to fp32 every 4 h4
#pragma unroll
        for (int j = 0; j < 4; ++j) {
            const int h4 = hb * 4 + j;
            const uint2 x  = hp[(size_t)h4 * SS];
            const __half2 xa = u2h(x.x), xb = u2h(x.y);
            const uint4 u0 = s0[h4];
            const uint4 u1 = s1[h4];
            const uint4 u2 = s2[h4];
            const uint4 u3 = s3[h4];
            acc[0] = __hfma2(u2h(u0.z), u2h(tanh2u(h2u(__hadd2(u2h(u0.x), xa)))), acc[0]);
            acc[0] = __hfma2(u2h(u0.w), u2h(tanh2u(h2u(__hadd2(u2h(u0.y), xb)))), acc[0]);
            acc[1] = __hfma2(u2h(u1.z), u2h(tanh2u(h2u(__hadd2(u2h(u1.x), xa)))), acc[1]);
            acc[1] = __hfma2(u2h(u1.w), u2h(tanh2u(h2u(__hadd2(u2h(u1.y), xb)))), acc[1]);
            acc[2] = __hfma2(u2h(u2.z), u2h(tanh2u(h2u(__hadd2(u2h(u2.x), xa)))), acc[2]);
            acc[2] = __hfma2(u2h(u2.w), u2h(tanh2u(h2u(__hadd2(u2h(u2.y), xb)))), acc[2]);
            acc[3] = __hfma2(u2h(u3.z), u2h(tanh2u(h2u(__hadd2(u2h(u3.x), xa)))), acc[3]);
            acc[3] = __hfma2(u2h(u3.w), u2h(tanh2u(h2u(__hadd2(u2h(u3.y), xb)))), acc[3]);
        }
#pragma unroll
        for (int r = 0; r < 4; ++r) {
            const float2 f = __half22float2(acc[r]);
            fa[r] += f.x + f.y;
            acc[r] = z;
        }
    }

#pragma unroll
    for (int r = 0; r < 4; ++r) {
        const float s = fa[r] + bav;
        const float p = __expf(0.5f * tanh_fast(0.5f * s) + 0.5f);
        g_p16[(size_t)(bt0 + r0 + r) * SS + tp] = __float2half(p);
    }
}

// ---------------------------------------------------------------------------
// Stage 3: output GEMM on tensor cores + in-block rowsum/normalize + wts.
// Block (mt, nt, b): rows mt*64..+64 of batch b, k-cols nt*64..+64.
//  Phase 1: rinv for the 64 rows from p16 (redundant across nt, deterministic).
//  Phase 2: wts slice (columns nt*128..+128) = p16 * rinv.
//  Phase 3: wmma GEMM, epilogue scales by rinv.
// ---------------------------------------------------------------------------
__global__ void __launch_bounds__(256)
out_wmma_kernel(float* __restrict__ out,
                float* __restrict__ wts)
{
    const int mt = blockIdx.x;          // 0..7  (t tile)
    const int nt = blockIdx.y;          // 0..3  (k tile)
    const int b  = blockIdx.z;          // batch

    const __half* __restrict__ A = g_p16 + (size_t)b * SS * SS;   // [t][tp]
    const __half* __restrict__ B = g_h16 + (size_t)b * SS * HH;   // [tp][k]

    const int tid  = threadIdx.x;
    const int warp = tid >> 5;
    const int lane = tid & 31;

    __shared__ float rinv[64];
    __shared__ float cs[64][68];

    // Phase 1: rowsums. Warp w owns local rows w*8 .. w*8+7.
#pragma unroll
    for (int i = 0; i < 8; ++i) {
        const int lr  = warp * 8 + i;
        const int row = mt * 64 + lr;
        const uint2* pr = reinterpret_cast<const uint2*>(A + (size_t)row * SS);
        float s = 0.f;
#pragma unroll
        for (int j = 0; j < 4; ++j) {
            const uint2 v = pr[lane + 32 * j];
            const float2 f0 = __half22float2(u2h(v.x));
            const float2 f1 = __half22float2(u2h(v.y));
            s += (f0.x + f0.y) + (f1.x + f1.y);
        }
#pragma unroll
        for (int off = 16; off > 0; off >>= 1)
            s += __shfl_xor_sync(0xffffffffu, s, off);
        if (lane == 0) rinv[lr] = 1.0f / s;
    }
    __syncthreads();

    // Phase 2: normalized weights, this block's 128-column slice.
    if (wts) {
        for (int e = tid; e < 64 * 32; e += 256) {
            const int r  = e >> 5;           // local row
            const int c  = e & 31;           // uint2 index within slice
            const int row = mt * 64 + r;
            const uint2 v = reinterpret_cast<const uint2*>(
                                A + (size_t)row * SS + nt * 128)[c];
            const float2 f0 = __half22float2(u2h(v.x));
            const float2 f1 = __half22float2(u2h(v.y));
            const float sc = rinv[r];
            float4 o;
            o.x = f0.x * sc; o.y = f0.y * sc; o.z = f1.x * sc; o.w = f1.y * sc;
            reinterpret_cast<float4*>(
                wts + (size_t)(b * SS + row) * SS + nt * 128)[c] = o;
        }
    }

    // Phase 3: GEMM.
    const int wm   = warp >> 1;
    const int wn   = warp & 1;
    const int row0 = mt * 64 + wm * 16;
    const int col0 = nt * 64 + wn * 32;

    wmma::fragment<wmma::accumulator, 16, 16, 16, float> c0, c1;
    wmma::fill_fragment(c0, 0.f);
    wmma::fill_fragment(c1, 0.f);

#pragma unroll 4
    for (int k = 0; k < SS; k += 16) {
        wmma::fragment<wmma::matrix_a, 16, 16, 16, __half, wmma::row_major> a;
        wmma::fragment<wmma::matrix_b, 16, 16, 16, __half, wmma::row_major> b0, b1;
        wmma::load_matrix_sync(a,  A + (size_t)row0 * SS + k, SS);
        wmma::load_matrix_sync(b0, B + (size_t)k * HH + col0,      HH);
        wmma::load_matrix_sync(b1, B + (size_t)k * HH + col0 + 16, HH);
        wmma::mma_sync(c0, a, b0, c0);
        wmma::mma_sync(c1, a, b1, c1);
    }

    wmma::store_matrix_sync(&cs[wm * 16][wn * 32],      c0, 68, wmma::mem_row_major);
    wmma::store_matrix_sync(&cs[wm * 16][wn * 32 + 16], c1, 68, wmma::mem_row_major);
    __syncthreads();

    for (int e = tid; e < 64 * 64; e += 256) {
        const int r = e >> 6, c = e & 63;
        const int bt  = b * SS + mt * 64 + r;
        const int col = nt * 64 + c;
        out[(size_t)bt * HH + col] = cs[r][c] * rinv[r];
    }
}

// ---------------------------------------------------------------------------
extern "C" void kernel_launch(void* const* d_in, const int* in_sizes, int n_in,
                              void* d_out, int out_size)
{
    const float* h   = (const float*)d_in[0];
    const float* Wt  = (const float*)d_in[1];
    const float* Wtp = (const float*)d_in[2];
    const float* bh  = (const float*)d_in[3];
    const float* Wa  = (const float*)d_in[4];
    const float* ba  = (const float*)d_in[5];

    float* out = (float*)d_out;
    float* wts = nullptr;
    const int nOut = BB * SS * HH;   // 524288
    const int nW   = BB * SS * SS;   // 1048576
    if (out_size >= nOut + nW) wts = out + nOut;

    convert_kernel<<<256, 256>>>(h, Wt, Wtp);
    proj_wmma_kernel<<<dim3(32, 4, 2), 256>>>(bh);
    score_kernel<<<dim3(SS / 32, BB * SS / 32), 256>>>(Wa, ba);
    out_wmma_kernel<<<dim3(8, 4, BB), 256>>>(out, wts);
}